// round 11
// baseline (speedup 1.0000x reference)
#include <cuda_runtime.h>
#include <cuda_bf16.h>
#include <cstdint>

// DeepFeatureLoss via mma.sync.m16n8k16 bf16 HMMA (feature) + fp32 spatial.
//   D_feat = cq_i(accum init) + 2L*f1_i.f2_j (3-term bf16 split, 6 ks) + cf_j
//   sp     = u_i . (2L u_j) + ci_i + cs_j            (fp32, epilogue)
//   eq = ex2(D_feat), ep = ex2(sp)
//   sum_j (p-q)^2 = Bb/Zp^2 - 2A/(Zp Zq) + C/Zq^2
// R11: rt=1 (MT=64) to kill register spills; 1024-block grid; launch order
// [prep_A, prep_B, init, main, reduce] so the profiler (abs idx 3) hits main.

#define SIGMA_INV 20.0f
#define LOG2E     1.4426950408889634f
#define KSH       44.0f
#define MAX_ROWS  16384
#define JCH       4
#define MT        64
#define NT        128

typedef unsigned long long ull;
typedef unsigned int  u32;
typedef unsigned short u16;

static __device__ __align__(16) u16 g_Af[(size_t)MAX_ROWS * 128];  // 64 u32/row, 48 used [ah|al|ah]
static __device__ __align__(16) u16 g_Bf[(size_t)MAX_ROWS * 128];  // [bh|bh|bl]
static __device__ __align__(16) float4 g_ui[MAX_ROWS];  // (u0,u1,u2, -L|u|^2)
static __device__ __align__(16) float4 g_vj[MAX_ROWS];  // (2L u0,2L u1,2L u2, -L|u|^2)
static __device__ float g_cf[MAX_ROWS];                 // -L|f2|^2
static __device__ float g_rc[MAX_ROWS];                 // KSH - L|f1|^2
static __device__ __align__(16) float4 g_part[(size_t)MAX_ROWS * JCH * 2];

// ---------- helpers ----------
__device__ __forceinline__ ull f2add(ull a, ull b) {
    ull d; asm("add.rn.f32x2 %0, %1, %2;" : "=l"(d) : "l"(a), "l"(b)); return d;
}
__device__ __forceinline__ ull f2fma(ull a, ull b, ull c) {
    ull d; asm("fma.rn.f32x2 %0, %1, %2, %3;" : "=l"(d) : "l"(a), "l"(b), "l"(c)); return d;
}
__device__ __forceinline__ float ex2f(float x) {
    float y; asm("ex2.approx.f32 %0, %1;" : "=f"(y) : "f"(x)); return y;
}
__device__ __forceinline__ void unpack2(ull v, float& lo, float& hi) {
    asm("mov.b64 {%0, %1}, %2;" : "=f"(lo), "=f"(hi) : "l"(v));
}
__device__ __forceinline__ void unpack2u(ull v, u32& lo, u32& hi) {
    asm("mov.b64 {%0, %1}, %2;" : "=r"(lo), "=r"(hi) : "l"(v));
}
__device__ __forceinline__ ull pack2(float lo, float hi) {
    ull v; asm("mov.b64 %0, {%1, %2};" : "=l"(v) : "f"(lo), "f"(hi)); return v;
}
__device__ __forceinline__ u16 f2bf(float x) {
    __nv_bfloat16 b = __float2bfloat16(x);
    return *reinterpret_cast<u16*>(&b);
}
__device__ __forceinline__ float bf2f(u16 u) {
    __nv_bfloat16 b = *reinterpret_cast<__nv_bfloat16*>(&u);
    return __bfloat162float(b);
}
__device__ __forceinline__ u32 pk(u16 lo, u16 hi) { return (u32)lo | ((u32)hi << 16); }

__device__ __forceinline__ void mma16816(float& d0, float& d1, float& d2, float& d3,
                                         const u32* a, u32 b0, u32 b1)
{
    asm("mma.sync.aligned.m16n8k16.row.col.f32.bf16.bf16.f32 "
        "{%0,%1,%2,%3},{%4,%5,%6,%7},{%8,%9},{%0,%1,%2,%3};"
        : "+f"(d0), "+f"(d1), "+f"(d2), "+f"(d3)
        : "r"(a[0]), "r"(a[1]), "r"(a[2]), "r"(a[3]), "r"(b0), "r"(b1));
}

// ---------- prep A: f1 splits + row consts ----------
__global__ void prep_A(const float* __restrict__ points,
                       const float* __restrict__ fea1, int BN)
{
    int g = blockIdx.x * 128 + threadIdx.x;
    if (g >= BN) return;

    float a[32]; float na = 0.f;
    const float4* F1 = (const float4*)(fea1 + (size_t)g * 32);
#pragma unroll
    for (int q = 0; q < 8; q++) {
        float4 v = F1[q];
        a[4*q] = v.x; a[4*q+1] = v.y; a[4*q+2] = v.z; a[4*q+3] = v.w;
        na = fmaf(v.x,v.x, fmaf(v.y,v.y, fmaf(v.z,v.z, fmaf(v.w,v.w, na))));
    }
    u16 ah[32], al[32];
#pragma unroll
    for (int k = 0; k < 32; k++) {
        ah[k] = f2bf(a[k]); al[k] = f2bf(a[k] - bf2f(ah[k]));
    }
    u32* Af = (u32*)&g_Af[(size_t)g * 128];
#pragma unroll
    for (int k = 0; k < 16; k++) {
        u32 h = pk(ah[2*k], ah[2*k+1]);
        Af[k] = h;
        Af[16 + k] = pk(al[2*k], al[2*k+1]);
        Af[32 + k] = h;
    }
    g_rc[g] = KSH - na * LOG2E;

    float u0 = points[(size_t)g*3+0] * SIGMA_INV;
    float u1 = points[(size_t)g*3+1] * SIGMA_INV;
    float u2 = points[(size_t)g*3+2] * SIGMA_INV;
    g_ui[g] = make_float4(u0, u1, u2, -(u0*u0 + u1*u1 + u2*u2) * LOG2E);
}

// ---------- prep B: f2 splits + col consts ----------
__global__ void prep_B(const float* __restrict__ points,
                       const float* __restrict__ fea2, int BN)
{
    int g = blockIdx.x * 128 + threadIdx.x;
    if (g >= BN) return;

    float bb[32]; float nb = 0.f;
    const float4* F2 = (const float4*)(fea2 + (size_t)g * 32);
#pragma unroll
    for (int q = 0; q < 8; q++) {
        float4 w = F2[q];
        nb = fmaf(w.x,w.x, fmaf(w.y,w.y, fmaf(w.z,w.z, fmaf(w.w,w.w, nb))));
        float s = 2.f * LOG2E;
        bb[4*q] = s*w.x; bb[4*q+1] = s*w.y; bb[4*q+2] = s*w.z; bb[4*q+3] = s*w.w;
    }
    u16 bh[32], bl[32];
#pragma unroll
    for (int k = 0; k < 32; k++) {
        bh[k] = f2bf(bb[k]); bl[k] = f2bf(bb[k] - bf2f(bh[k]));
    }
    u32* Bf = (u32*)&g_Bf[(size_t)g * 128];
#pragma unroll
    for (int k = 0; k < 16; k++) {
        u32 h = pk(bh[2*k], bh[2*k+1]);
        Bf[k] = h;
        Bf[16 + k] = h;
        Bf[32 + k] = pk(bl[2*k], bl[2*k+1]);
    }
    g_cf[g] = -nb * LOG2E;

    float u0 = points[(size_t)g*3+0] * SIGMA_INV;
    float u1 = points[(size_t)g*3+1] * SIGMA_INV;
    float u2 = points[(size_t)g*3+2] * SIGMA_INV;
    float s = 2.f * LOG2E;
    g_vj[g] = make_float4(s*u0, s*u1, s*u2, -(u0*u0 + u1*u1 + u2*u2) * LOG2E);
}

// ---------- init ----------
__global__ void init_kernel(float* out, int B)
{
    if (threadIdx.x < B) out[threadIdx.x] = 0.f;
}

// ---------- main (rt=1, MT=64) ----------
__global__ __launch_bounds__(128) void main_kernel(int N)
{
    __shared__ __align__(16) ull sBfU[128 * 32];   // paired+rotated feature B
    __shared__ __align__(16) float4 sVj[128];
    __shared__ float sCf[128];

    const int tid = threadIdx.x;
    const int w = tid >> 5, l = tid & 31, g = l >> 2, t = l & 3;
    const int rowtile = blockIdx.x >> 2;           // / JCH
    const int chunk   = blockIdx.x & 3;
    const int rowbase = rowtile * MT;
    const int b  = rowbase / N;
    const int jc = N / JCH;                        // 1024
    const int j0 = b * N + chunk * jc;
    const int ntiles = jc / NT;                    // 8

    const u32* Af = (const u32*)g_Af;

    // A fragments: rows r0 = rowbase + 16w + g and r0+8
    const int r0 = rowbase + 16 * w + g;
    u32 af[6][4];
#pragma unroll
    for (int ks = 0; ks < 6; ks++) {
        af[ks][0] = Af[(size_t)r0 * 64 + t + 8 * ks];
        af[ks][1] = Af[(size_t)(r0 + 8) * 64 + t + 8 * ks];
        af[ks][2] = Af[(size_t)r0 * 64 + t + 4 + 8 * ks];
        af[ks][3] = Af[(size_t)(r0 + 8) * 64 + t + 4 + 8 * ks];
    }
    const float cq0 = g_rc[r0], cq1 = g_rc[r0 + 8];
    const float4 u_h0 = g_ui[r0];
    const float4 u_h1 = g_ui[r0 + 8];

    ull Z[2] = {0,0}, S[2] = {0,0};
    float Aa[2] = {0.f, 0.f};

    for (int jt = 0; jt < ntiles; jt++) {
        __syncthreads();
        const int jrow = j0 + jt * NT;
        // stage feature B: thread = row (paired ull + rotation, conflict-free)
        {
            const uint4* src = (const uint4*)&g_Bf[(size_t)(jrow + tid) * 128];
            ull* dstrow = &sBfU[tid * 32];
            const int rot4 = 4 * (tid & 7);
#pragma unroll
            for (int u = 0; u < 6; u++) {
                uint4 lo = src[2 * u], hi = src[2 * u + 1];
                int base = (4 * u + rot4) & 31;
                *(uint4*)&dstrow[base]     = make_uint4(lo.x, hi.x, lo.y, hi.y);
                *(uint4*)&dstrow[base + 2] = make_uint4(lo.z, hi.z, lo.w, hi.w);
            }
            sVj[tid] = g_vj[jrow + tid];
            sCf[tid] = g_cf[jrow + tid];
        }
        __syncthreads();

#pragma unroll 1
        for (int ns = 0; ns < 16; ns++) {
            const int n = ns * 8 + g;
            const ull* rowF = &sBfU[n * 32];
            ull F[6];
#pragma unroll
            for (int ks = 0; ks < 6; ks++)
                F[ks] = rowF[(4 * ks + t + 4 * g) & 31];

            const int c0 = ns * 8 + 2 * t;
            float4 vA = sVj[c0];
            float4 vB = sVj[c0 + 1];
            float2 cf2 = *(const float2*)&sCf[c0];

            // feature: single 6-step chain, accum init = cq
            float d0 = cq0, d1 = cq0, d2 = cq1, d3 = cq1;
#pragma unroll
            for (int ks = 0; ks < 6; ks++) {
                u32 lo, hi; unpack2u(F[ks], lo, hi);
                mma16816(d0, d1, d2, d3, af[ks], lo, hi);
            }

            // spatial fp32 + accumulate
            {
                float sq = d0 + cf2.x;
                float sp = fmaf(u_h0.x, vA.x, fmaf(u_h0.y, vA.y,
                           fmaf(u_h0.z, vA.z, u_h0.w + vA.w)));
                float eq = ex2f(sq), ep = ex2f(sp);
                ull e = pack2(eq, ep);
                Z[0] = f2add(Z[0], e); S[0] = f2fma(e, e, S[0]);
                Aa[0] = fmaf(ep, eq, Aa[0]);
            }
            {
                float sq = d1 + cf2.y;
                float sp = fmaf(u_h0.x, vB.x, fmaf(u_h0.y, vB.y,
                           fmaf(u_h0.z, vB.z, u_h0.w + vB.w)));
                float eq = ex2f(sq), ep = ex2f(sp);
                ull e = pack2(eq, ep);
                Z[0] = f2add(Z[0], e); S[0] = f2fma(e, e, S[0]);
                Aa[0] = fmaf(ep, eq, Aa[0]);
            }
            {
                float sq = d2 + cf2.x;
                float sp = fmaf(u_h1.x, vA.x, fmaf(u_h1.y, vA.y,
                           fmaf(u_h1.z, vA.z, u_h1.w + vA.w)));
                float eq = ex2f(sq), ep = ex2f(sp);
                ull e = pack2(eq, ep);
                Z[1] = f2add(Z[1], e); S[1] = f2fma(e, e, S[1]);
                Aa[1] = fmaf(ep, eq, Aa[1]);
            }
            {
                float sq = d3 + cf2.y;
                float sp = fmaf(u_h1.x, vB.x, fmaf(u_h1.y, vB.y,
                           fmaf(u_h1.z, vB.z, u_h1.w + vB.w)));
                float eq = ex2f(sq), ep = ex2f(sp);
                ull e = pack2(eq, ep);
                Z[1] = f2add(Z[1], e); S[1] = f2fma(e, e, S[1]);
                Aa[1] = fmaf(ep, eq, Aa[1]);
            }
        }
    }

    // quad-reduce over t, write partials for rows r0 and r0+8
#pragma unroll
    for (int h = 0; h < 2; h++) {
        float Zq, Zp, C, Bb;
        unpack2(Z[h], Zq, Zp);
        unpack2(S[h], C, Bb);
        float A_ = Aa[h];
#pragma unroll
        for (int m = 1; m <= 2; m <<= 1) {
            Zq += __shfl_xor_sync(0xffffffffu, Zq, m);
            Zp += __shfl_xor_sync(0xffffffffu, Zp, m);
            C  += __shfl_xor_sync(0xffffffffu, C,  m);
            Bb += __shfl_xor_sync(0xffffffffu, Bb, m);
            A_ += __shfl_xor_sync(0xffffffffu, A_, m);
        }
        if (t == 0) {
            int row = r0 + 8 * h;
            size_t p = ((size_t)row * JCH + chunk) * 2;
            g_part[p + 0] = make_float4(Zq, A_, C, Zp);
            g_part[p + 1] = make_float4(Bb, 0.f, 0.f, 0.f);
        }
    }
}

// ---------- reduce: 4 threads per row ----------
__global__ __launch_bounds__(128) void reduce_kernel(
    const float* __restrict__ weights,
    float* __restrict__ out, int N)
{
    __shared__ float sred[4];
    const int tid = threadIdx.x;
    const int r = blockIdx.x * 32 + (tid >> 2);
    const int t = tid & 3;
    const int b = (blockIdx.x * 32) / N;

    const float4* base = &g_part[(size_t)r * JCH * 2];
    float4 p0 = base[2 * t + 0];
    float4 p1 = base[2 * t + 1];
    float Zq = p0.x, A = p0.y, C = p0.z, Zp = p0.w, Bb = p1.x;

#pragma unroll
    for (int m = 1; m <= 2; m <<= 1) {
        Zq += __shfl_xor_sync(0xffffffffu, Zq, m);
        Zp += __shfl_xor_sync(0xffffffffu, Zp, m);
        C  += __shfl_xor_sync(0xffffffffu, C,  m);
        Bb += __shfl_xor_sync(0xffffffffu, Bb, m);
        A  += __shfl_xor_sync(0xffffffffu, A,  m);
    }
    float v = 0.f;
    if (t == 0) {
        float izp = 1.f / Zp, izq = 1.f / Zq;
        float loss = Bb * izp * izp - 2.f * A * izp * izq + C * izq * izq;
        v = weights[r] * loss;
    }
#pragma unroll
    for (int off = 16; off > 0; off >>= 1)
        v += __shfl_down_sync(0xffffffffu, v, off);
    if ((tid & 31) == 0) sred[tid >> 5] = v;
    __syncthreads();
    if (tid == 0) {
        atomicAdd(&out[b], sred[0] + sred[1] + sred[2] + sred[3]);
    }
}

extern "C" void kernel_launch(void* const* d_in, const int* in_sizes, int n_in,
                              void* d_out, int out_size)
{
    const float* points  = (const float*)d_in[0];  // [B,N,3]
    const float* fea1    = (const float*)d_in[1];  // [B,N,32]
    const float* fea2    = (const float*)d_in[2];  // [B,N,32]
    const float* weights = (const float*)d_in[3];  // [B,N]

    int BN = in_sizes[3];
    int B  = out_size;
    int N  = BN / B;

    // Launch order: main is absolute launch index 3 (the profiled one).
    prep_A<<<(BN + 127) / 128, 128>>>(points, fea1, BN);
    prep_B<<<(BN + 127) / 128, 128>>>(points, fea2, BN);
    init_kernel<<<1, 32>>>((float*)d_out, B);

    int rowtiles = BN / MT;                       // 256
    main_kernel<<<rowtiles * JCH, 128>>>(N);      // 1024 blocks

    reduce_kernel<<<BN / 32, 128>>>(weights, (float*)d_out, N);
}

// round 12
// speedup vs baseline: 1.5780x; 1.5780x over previous
#include <cuda_runtime.h>
#include <cuda_bf16.h>
#include <cstdint>

// DeepFeatureLoss via mma.sync.m16n8k16 bf16 HMMA (feature) + fp32 spatial.
//   D_feat = cq_i(accum init) + 2L*f1_i.f2_j (3 cross terms ah*bh+al*bh+ah*bl,
//            deduplicated operand storage [ah|al], [bh|bl]; 6 MMAs) + cf_j
//   sp     = u_i . (2L u_j) + ci_i + cs_j   (fp32, epilogue)
//   eq = ex2(D_feat), ep = ex2(sp)
//   sum_j (p-q)^2 = Bb/Zp^2 - 2A/(Zp Zq) + C/Zq^2
// R12: rt=2 (MT=128, reuse), JCH=16 (grid 1024), dedup operands (af 48->32
// regs, F 6->4 LDS, staging halved). Launch order keeps main at abs idx 3.

#define SIGMA_INV 20.0f
#define LOG2E     1.4426950408889634f
#define KSH       44.0f
#define MAX_ROWS  16384
#define JCH       16
#define MT        128
#define NT        128

typedef unsigned long long ull;
typedef unsigned int  u32;
typedef unsigned short u16;

static __device__ __align__(16) u16 g_Af[(size_t)MAX_ROWS * 64];  // 32 u32/row: [ah|al]
static __device__ __align__(16) u16 g_Bf[(size_t)MAX_ROWS * 64];  // 32 u32/row: [bh|bl]
static __device__ __align__(16) float4 g_ui[MAX_ROWS];  // (u0,u1,u2, -L|u|^2)
static __device__ __align__(16) float4 g_vj[MAX_ROWS];  // (2L u0,2L u1,2L u2, -L|u|^2)
static __device__ float g_cf[MAX_ROWS];                 // -L|f2|^2
static __device__ float g_rc[MAX_ROWS];                 // KSH - L|f1|^2
static __device__ __align__(16) float4 g_part[(size_t)MAX_ROWS * JCH * 2];

// ---------- helpers ----------
__device__ __forceinline__ ull f2add(ull a, ull b) {
    ull d; asm("add.rn.f32x2 %0, %1, %2;" : "=l"(d) : "l"(a), "l"(b)); return d;
}
__device__ __forceinline__ ull f2fma(ull a, ull b, ull c) {
    ull d; asm("fma.rn.f32x2 %0, %1, %2, %3;" : "=l"(d) : "l"(a), "l"(b), "l"(c)); return d;
}
__device__ __forceinline__ float ex2f(float x) {
    float y; asm("ex2.approx.f32 %0, %1;" : "=f"(y) : "f"(x)); return y;
}
__device__ __forceinline__ void unpack2(ull v, float& lo, float& hi) {
    asm("mov.b64 {%0, %1}, %2;" : "=f"(lo), "=f"(hi) : "l"(v));
}
__device__ __forceinline__ void unpack2u(ull v, u32& lo, u32& hi) {
    asm("mov.b64 {%0, %1}, %2;" : "=r"(lo), "=r"(hi) : "l"(v));
}
__device__ __forceinline__ ull pack2(float lo, float hi) {
    ull v; asm("mov.b64 %0, {%1, %2};" : "=l"(v) : "f"(lo), "f"(hi)); return v;
}
__device__ __forceinline__ u16 f2bf(float x) {
    __nv_bfloat16 b = __float2bfloat16(x);
    return *reinterpret_cast<u16*>(&b);
}
__device__ __forceinline__ float bf2f(u16 u) {
    __nv_bfloat16 b = *reinterpret_cast<__nv_bfloat16*>(&u);
    return __bfloat162float(b);
}
__device__ __forceinline__ u32 pk(u16 lo, u16 hi) { return (u32)lo | ((u32)hi << 16); }

__device__ __forceinline__ void mma16816(float& d0, float& d1, float& d2, float& d3,
                                         const u32* a, u32 b0, u32 b1)
{
    asm("mma.sync.aligned.m16n8k16.row.col.f32.bf16.bf16.f32 "
        "{%0,%1,%2,%3},{%4,%5,%6,%7},{%8,%9},{%0,%1,%2,%3};"
        : "+f"(d0), "+f"(d1), "+f"(d2), "+f"(d3)
        : "r"(a[0]), "r"(a[1]), "r"(a[2]), "r"(a[3]), "r"(b0), "r"(b1));
}

// ---------- prep A: f1 splits [ah|al] + row consts ----------
__global__ void prep_A(const float* __restrict__ points,
                       const float* __restrict__ fea1, int BN)
{
    int g = blockIdx.x * 128 + threadIdx.x;
    if (g >= BN) return;

    float a[32]; float na = 0.f;
    const float4* F1 = (const float4*)(fea1 + (size_t)g * 32);
#pragma unroll
    for (int q = 0; q < 8; q++) {
        float4 v = F1[q];
        a[4*q] = v.x; a[4*q+1] = v.y; a[4*q+2] = v.z; a[4*q+3] = v.w;
        na = fmaf(v.x,v.x, fmaf(v.y,v.y, fmaf(v.z,v.z, fmaf(v.w,v.w, na))));
    }
    u32* Af = (u32*)&g_Af[(size_t)g * 64];
#pragma unroll
    for (int k = 0; k < 16; k++) {
        u16 h0 = f2bf(a[2*k]),   l0 = f2bf(a[2*k]   - bf2f(f2bf(a[2*k])));
        u16 h1 = f2bf(a[2*k+1]), l1 = f2bf(a[2*k+1] - bf2f(f2bf(a[2*k+1])));
        Af[k]      = pk(h0, h1);
        Af[16 + k] = pk(l0, l1);
    }
    g_rc[g] = KSH - na * LOG2E;

    float u0 = points[(size_t)g*3+0] * SIGMA_INV;
    float u1 = points[(size_t)g*3+1] * SIGMA_INV;
    float u2 = points[(size_t)g*3+2] * SIGMA_INV;
    g_ui[g] = make_float4(u0, u1, u2, -(u0*u0 + u1*u1 + u2*u2) * LOG2E);
}

// ---------- prep B: f2 splits [bh|bl] + col consts ----------
__global__ void prep_B(const float* __restrict__ points,
                       const float* __restrict__ fea2, int BN)
{
    int g = blockIdx.x * 128 + threadIdx.x;
    if (g >= BN) return;

    float bb[32]; float nb = 0.f;
    const float4* F2 = (const float4*)(fea2 + (size_t)g * 32);
#pragma unroll
    for (int q = 0; q < 8; q++) {
        float4 w = F2[q];
        nb = fmaf(w.x,w.x, fmaf(w.y,w.y, fmaf(w.z,w.z, fmaf(w.w,w.w, nb))));
        float s = 2.f * LOG2E;
        bb[4*q] = s*w.x; bb[4*q+1] = s*w.y; bb[4*q+2] = s*w.z; bb[4*q+3] = s*w.w;
    }
    u32* Bf = (u32*)&g_Bf[(size_t)g * 64];
#pragma unroll
    for (int k = 0; k < 16; k++) {
        u16 h0 = f2bf(bb[2*k]),   l0 = f2bf(bb[2*k]   - bf2f(f2bf(bb[2*k])));
        u16 h1 = f2bf(bb[2*k+1]), l1 = f2bf(bb[2*k+1] - bf2f(f2bf(bb[2*k+1])));
        Bf[k]      = pk(h0, h1);
        Bf[16 + k] = pk(l0, l1);
    }
    g_cf[g] = -nb * LOG2E;

    float u0 = points[(size_t)g*3+0] * SIGMA_INV;
    float u1 = points[(size_t)g*3+1] * SIGMA_INV;
    float u2 = points[(size_t)g*3+2] * SIGMA_INV;
    float s = 2.f * LOG2E;
    g_vj[g] = make_float4(s*u0, s*u1, s*u2, -(u0*u0 + u1*u1 + u2*u2) * LOG2E);
}

// ---------- init ----------
__global__ void init_kernel(float* out, int B)
{
    if (threadIdx.x < B) out[threadIdx.x] = 0.f;
}

// ---------- main (rt=2, MT=128, dedup operands) ----------
__global__ __launch_bounds__(128) void main_kernel(int N)
{
    // feature B: 128 rows x 16 ull (paired b0b1 + 4*(row&3) rotation)
    __shared__ __align__(16) ull sBfU[128 * 16];
    __shared__ __align__(16) float4 sVj[128];
    __shared__ float sCf[128];

    const int tid = threadIdx.x;
    const int w = tid >> 5, l = tid & 31, g = l >> 2, t = l & 3;
    const int rowtile = blockIdx.x >> 4;
    const int chunk   = blockIdx.x & 15;
    const int rowbase = rowtile * MT;
    const int b  = rowbase / N;
    const int jc = N / JCH;                 // 256
    const int j0 = b * N + chunk * jc;
    const int ntiles = jc / NT;             // 2

    const u32* Af = (const u32*)g_Af;

    // A fragments: 4 distinct k-groups per rt: (ah,ks0)(ah,ks1)(al,ks0)(al,ks1)
    u32 af[2][4][4];
    float cq[4];
    float4 u_h[4];
#pragma unroll
    for (int rt = 0; rt < 2; rt++) {
        int r0 = rowbase + 32 * w + 16 * rt + g;
#pragma unroll
        for (int q = 0; q < 4; q++) {
            int wbase = 8 * q + t;          // q0: ah ks0, q1: ah ks1, q2: al ks0, q3: al ks1
            af[rt][q][0] = Af[(size_t)r0 * 32 + wbase];
            af[rt][q][1] = Af[(size_t)(r0 + 8) * 32 + wbase];
            af[rt][q][2] = Af[(size_t)r0 * 32 + wbase + 4];
            af[rt][q][3] = Af[(size_t)(r0 + 8) * 32 + wbase + 4];
        }
        cq[2*rt]     = g_rc[r0];
        cq[2*rt + 1] = g_rc[r0 + 8];
        u_h[2*rt]     = g_ui[r0];
        u_h[2*rt + 1] = g_ui[r0 + 8];
    }

    ull Z[4] = {0,0,0,0}, S[4] = {0,0,0,0};
    float Aa[4] = {0.f, 0.f, 0.f, 0.f};

    for (int jt = 0; jt < ntiles; jt++) {
        __syncthreads();
        const int jrow = j0 + jt * NT;
        // stage feature B: thread = row; 8 uint4 -> 16 paired ulls, rotated
        {
            const uint4* src = (const uint4*)&g_Bf[(size_t)(jrow + tid) * 64];
            ull* dstrow = &sBfU[tid * 16];
            const int rot4 = 4 * (tid & 3);
#pragma unroll
            for (int u = 0; u < 4; u++) {
                uint4 lo = src[2 * u], hi = src[2 * u + 1];
                int base = (4 * u + rot4) & 15;         // multiple of 4, no wrap
                *(uint4*)&dstrow[base]     = make_uint4(lo.x, hi.x, lo.y, hi.y);
                *(uint4*)&dstrow[base + 2] = make_uint4(lo.z, hi.z, lo.w, hi.w);
            }
            sVj[tid] = g_vj[jrow + tid];
            sCf[tid] = g_cf[jrow + tid];
        }
        __syncthreads();

#pragma unroll 2
        for (int ns = 0; ns < 16; ns++) {
            const int n = ns * 8 + g;
            const ull* rowF = &sBfU[n * 16];
            const int rot = 4 * (g & 3);    // (n & 3) == (g & 3)
            ull Fbh0 = rowF[(t + rot) & 15];
            ull Fbh1 = rowF[(4 + t + rot) & 15];
            ull Fbl0 = rowF[(8 + t + rot) & 15];
            ull Fbl1 = rowF[(12 + t + rot) & 15];

            const int c0 = ns * 8 + 2 * t;
            float4 vA = sVj[c0];
            float4 vB = sVj[c0 + 1];
            float2 cf2 = *(const float2*)&sCf[c0];

#pragma unroll
            for (int rt = 0; rt < 2; rt++) {
                const int h0 = 2 * rt, h1 = 2 * rt + 1;
                u32 bh0l, bh0h, bh1l, bh1h, bl0l, bl0h, bl1l, bl1h;
                unpack2u(Fbh0, bh0l, bh0h);
                unpack2u(Fbh1, bh1l, bh1h);
                unpack2u(Fbl0, bl0l, bl0h);
                unpack2u(Fbl1, bl1l, bl1h);

                // two independent 3-MMA chains: ah*bh+al*bh and ah*bl
                float a0 = cq[h0], a1 = cq[h0], a2 = cq[h1], a3 = cq[h1];
                float b0 = 0.f, b1 = 0.f, b2 = 0.f, b3 = 0.f;
                mma16816(a0, a1, a2, a3, af[rt][0], bh0l, bh0h);   // ah ks0 * bh ks0
                mma16816(b0, b1, b2, b3, af[rt][1], bh1l, bh1h);   // ah ks1 * bh ks1
                mma16816(a0, a1, a2, a3, af[rt][2], bh0l, bh0h);   // al ks0 * bh ks0
                mma16816(b0, b1, b2, b3, af[rt][3], bh1l, bh1h);   // al ks1 * bh ks1
                mma16816(a0, a1, a2, a3, af[rt][0], bl0l, bl0h);   // ah ks0 * bl ks0
                mma16816(b0, b1, b2, b3, af[rt][1], bl1l, bl1h);   // ah ks1 * bl ks1

                {
                    float sq = (a0 + b0) + cf2.x;
                    float sp = fmaf(u_h[h0].x, vA.x, fmaf(u_h[h0].y, vA.y,
                               fmaf(u_h[h0].z, vA.z, u_h[h0].w + vA.w)));
                    float eq = ex2f(sq), ep = ex2f(sp);
                    ull e = pack2(eq, ep);
                    Z[h0] = f2add(Z[h0], e); S[h0] = f2fma(e, e, S[h0]);
                    Aa[h0] = fmaf(ep, eq, Aa[h0]);
                }
                {
                    float sq = (a1 + b1) + cf2.y;
                    float sp = fmaf(u_h[h0].x, vB.x, fmaf(u_h[h0].y, vB.y,
                               fmaf(u_h[h0].z, vB.z, u_h[h0].w + vB.w)));
                    float eq = ex2f(sq), ep = ex2f(sp);
                    ull e = pack2(eq, ep);
                    Z[h0] = f2add(Z[h0], e); S[h0] = f2fma(e, e, S[h0]);
                    Aa[h0] = fmaf(ep, eq, Aa[h0]);
                }
                {
                    float sq = (a2 + b2) + cf2.x;
                    float sp = fmaf(u_h[h1].x, vA.x, fmaf(u_h[h1].y, vA.y,
                               fmaf(u_h[h1].z, vA.z, u_h[h1].w + vA.w)));
                    float eq = ex2f(sq), ep = ex2f(sp);
                    ull e = pack2(eq, ep);
                    Z[h1] = f2add(Z[h1], e); S[h1] = f2fma(e, e, S[h1]);
                    Aa[h1] = fmaf(ep, eq, Aa[h1]);
                }
                {
                    float sq = (a3 + b3) + cf2.y;
                    float sp = fmaf(u_h[h1].x, vB.x, fmaf(u_h[h1].y, vB.y,
                               fmaf(u_h[h1].z, vB.z, u_h[h1].w + vB.w)));
                    float eq = ex2f(sq), ep = ex2f(sp);
                    ull e = pack2(eq, ep);
                    Z[h1] = f2add(Z[h1], e); S[h1] = f2fma(e, e, S[h1]);
                    Aa[h1] = fmaf(ep, eq, Aa[h1]);
                }
            }
        }
    }

    // quad-reduce over t, write partials
#pragma unroll
    for (int h = 0; h < 4; h++) {
        float Zq, Zp, C, Bb;
        unpack2(Z[h], Zq, Zp);
        unpack2(S[h], C, Bb);
        float A_ = Aa[h];
#pragma unroll
        for (int m = 1; m <= 2; m <<= 1) {
            Zq += __shfl_xor_sync(0xffffffffu, Zq, m);
            Zp += __shfl_xor_sync(0xffffffffu, Zp, m);
            C  += __shfl_xor_sync(0xffffffffu, C,  m);
            Bb += __shfl_xor_sync(0xffffffffu, Bb, m);
            A_ += __shfl_xor_sync(0xffffffffu, A_, m);
        }
        if (t == 0) {
            int row = rowbase + 32 * w + 16 * (h >> 1) + 8 * (h & 1) + g;
            size_t p = ((size_t)row * JCH + chunk) * 2;
            g_part[p + 0] = make_float4(Zq, A_, C, Zp);
            g_part[p + 1] = make_float4(Bb, 0.f, 0.f, 0.f);
        }
    }
}

// ---------- reduce: 4 threads per row, 16 chunks ----------
__global__ __launch_bounds__(128) void reduce_kernel(
    const float* __restrict__ weights,
    float* __restrict__ out, int N)
{
    __shared__ float sred[4];
    const int tid = threadIdx.x;
    const int r = blockIdx.x * 32 + (tid >> 2);
    const int t = tid & 3;
    const int b = (blockIdx.x * 32) / N;

    const float4* base = &g_part[(size_t)r * JCH * 2];
    float Zq = 0.f, A = 0.f, C = 0.f, Zp = 0.f, Bb = 0.f;
#pragma unroll
    for (int kk = 0; kk < 4; kk++) {
        int k = t + 4 * kk;
        float4 p0 = base[2 * k + 0];
        float4 p1 = base[2 * k + 1];
        Zq += p0.x; A += p0.y; C += p0.z; Zp += p0.w; Bb += p1.x;
    }
#pragma unroll
    for (int m = 1; m <= 2; m <<= 1) {
        Zq += __shfl_xor_sync(0xffffffffu, Zq, m);
        Zp += __shfl_xor_sync(0xffffffffu, Zp, m);
        C  += __shfl_xor_sync(0xffffffffu, C,  m);
        Bb += __shfl_xor_sync(0xffffffffu, Bb, m);
        A  += __shfl_xor_sync(0xffffffffu, A,  m);
    }
    float v = 0.f;
    if (t == 0) {
        float izp = 1.f / Zp, izq = 1.f / Zq;
        float loss = Bb * izp * izp - 2.f * A * izp * izq + C * izq * izq;
        v = weights[r] * loss;
    }
#pragma unroll
    for (int off = 16; off > 0; off >>= 1)
        v += __shfl_down_sync(0xffffffffu, v, off);
    if ((tid & 31) == 0) sred[tid >> 5] = v;
    __syncthreads();
    if (tid == 0) {
        atomicAdd(&out[b], sred[0] + sred[1] + sred[2] + sred[3]);
    }
}

extern "C" void kernel_launch(void* const* d_in, const int* in_sizes, int n_in,
                              void* d_out, int out_size)
{
    const float* points  = (const float*)d_in[0];  // [B,N,3]
    const float* fea1    = (const float*)d_in[1];  // [B,N,32]
    const float* fea2    = (const float*)d_in[2];  // [B,N,32]
    const float* weights = (const float*)d_in[3];  // [B,N]

    int BN = in_sizes[3];
    int B  = out_size;
    int N  = BN / B;

    // main is absolute launch index 3 (the profiled slot).
    prep_A<<<(BN + 127) / 128, 128>>>(points, fea1, BN);
    prep_B<<<(BN + 127) / 128, 128>>>(points, fea2, BN);
    init_kernel<<<1, 32>>>((float*)d_out, B);

    int rowtiles = BN / MT;                       // 64
    main_kernel<<<rowtiles * JCH, 128>>>(N);      // 1024 blocks

    reduce_kernel<<<BN / 32, 128>>>(weights, (float*)d_out, N);
}

// round 13
// speedup vs baseline: 1.5990x; 1.0133x over previous
#include <cuda_runtime.h>
#include <cuda_bf16.h>
#include <cstdint>

// DeepFeatureLoss via mma.sync.m16n8k16 bf16 HMMA (feature) + fp32 spatial.
//   D_feat = cq_i(chainA init) + 2L*f1_i.f2_j (dedup 3-cross-term split,
//            6 MMAs in two 3-chains) + cf_j(chainB init)
//   sp     = u_i . (2L u_j) + ci_i + cs_j   (fp32, epilogue)
//   eq = ex2(D_feat), ep = ex2(sp)
//   sum_j (p-q)^2 = Bb/Zp^2 - 2A/(Zp Zq) + C/Zq^2
// R13: launch_bounds(128,4) (occ 17->23%), cf_j folded into MMA accumulator
// init (-8 FADD/iter), hoisted LDS offsets. Main stays at abs launch idx 3.

#define SIGMA_INV 20.0f
#define LOG2E     1.4426950408889634f
#define KSH       44.0f
#define MAX_ROWS  16384
#define JCH       16
#define MT        128
#define NT        128

typedef unsigned long long ull;
typedef unsigned int  u32;
typedef unsigned short u16;

static __device__ __align__(16) u16 g_Af[(size_t)MAX_ROWS * 64];  // 32 u32/row: [ah|al]
static __device__ __align__(16) u16 g_Bf[(size_t)MAX_ROWS * 64];  // 32 u32/row: [bh|bl]
static __device__ __align__(16) float4 g_ui[MAX_ROWS];  // (u0,u1,u2, -L|u|^2)
static __device__ __align__(16) float4 g_vj[MAX_ROWS];  // (2L u0,2L u1,2L u2, -L|u|^2)
static __device__ float g_cf[MAX_ROWS];                 // -L|f2|^2
static __device__ float g_rc[MAX_ROWS];                 // KSH - L|f1|^2
static __device__ __align__(16) float4 g_part[(size_t)MAX_ROWS * JCH * 2];

// ---------- helpers ----------
__device__ __forceinline__ ull f2add(ull a, ull b) {
    ull d; asm("add.rn.f32x2 %0, %1, %2;" : "=l"(d) : "l"(a), "l"(b)); return d;
}
__device__ __forceinline__ ull f2fma(ull a, ull b, ull c) {
    ull d; asm("fma.rn.f32x2 %0, %1, %2, %3;" : "=l"(d) : "l"(a), "l"(b), "l"(c)); return d;
}
__device__ __forceinline__ float ex2f(float x) {
    float y; asm("ex2.approx.f32 %0, %1;" : "=f"(y) : "f"(x)); return y;
}
__device__ __forceinline__ void unpack2(ull v, float& lo, float& hi) {
    asm("mov.b64 {%0, %1}, %2;" : "=f"(lo), "=f"(hi) : "l"(v));
}
__device__ __forceinline__ void unpack2u(ull v, u32& lo, u32& hi) {
    asm("mov.b64 {%0, %1}, %2;" : "=r"(lo), "=r"(hi) : "l"(v));
}
__device__ __forceinline__ ull pack2(float lo, float hi) {
    ull v; asm("mov.b64 %0, {%1, %2};" : "=l"(v) : "f"(lo), "f"(hi)); return v;
}
__device__ __forceinline__ u16 f2bf(float x) {
    __nv_bfloat16 b = __float2bfloat16(x);
    return *reinterpret_cast<u16*>(&b);
}
__device__ __forceinline__ float bf2f(u16 u) {
    __nv_bfloat16 b = *reinterpret_cast<__nv_bfloat16*>(&u);
    return __bfloat162float(b);
}
__device__ __forceinline__ u32 pk(u16 lo, u16 hi) { return (u32)lo | ((u32)hi << 16); }

__device__ __forceinline__ void mma16816(float& d0, float& d1, float& d2, float& d3,
                                         const u32* a, u32 b0, u32 b1)
{
    asm("mma.sync.aligned.m16n8k16.row.col.f32.bf16.bf16.f32 "
        "{%0,%1,%2,%3},{%4,%5,%6,%7},{%8,%9},{%0,%1,%2,%3};"
        : "+f"(d0), "+f"(d1), "+f"(d2), "+f"(d3)
        : "r"(a[0]), "r"(a[1]), "r"(a[2]), "r"(a[3]), "r"(b0), "r"(b1));
}

// ---------- prep A: f1 splits [ah|al] + row consts ----------
__global__ void prep_A(const float* __restrict__ points,
                       const float* __restrict__ fea1, int BN)
{
    int g = blockIdx.x * 128 + threadIdx.x;
    if (g >= BN) return;

    float a[32]; float na = 0.f;
    const float4* F1 = (const float4*)(fea1 + (size_t)g * 32);
#pragma unroll
    for (int q = 0; q < 8; q++) {
        float4 v = F1[q];
        a[4*q] = v.x; a[4*q+1] = v.y; a[4*q+2] = v.z; a[4*q+3] = v.w;
        na = fmaf(v.x,v.x, fmaf(v.y,v.y, fmaf(v.z,v.z, fmaf(v.w,v.w, na))));
    }
    u32* Af = (u32*)&g_Af[(size_t)g * 64];
#pragma unroll
    for (int k = 0; k < 16; k++) {
        u16 h0 = f2bf(a[2*k]),   l0 = f2bf(a[2*k]   - bf2f(f2bf(a[2*k])));
        u16 h1 = f2bf(a[2*k+1]), l1 = f2bf(a[2*k+1] - bf2f(f2bf(a[2*k+1])));
        Af[k]      = pk(h0, h1);
        Af[16 + k] = pk(l0, l1);
    }
    g_rc[g] = KSH - na * LOG2E;

    float u0 = points[(size_t)g*3+0] * SIGMA_INV;
    float u1 = points[(size_t)g*3+1] * SIGMA_INV;
    float u2 = points[(size_t)g*3+2] * SIGMA_INV;
    g_ui[g] = make_float4(u0, u1, u2, -(u0*u0 + u1*u1 + u2*u2) * LOG2E);
}

// ---------- prep B: f2 splits [bh|bl] + col consts ----------
__global__ void prep_B(const float* __restrict__ points,
                       const float* __restrict__ fea2, int BN)
{
    int g = blockIdx.x * 128 + threadIdx.x;
    if (g >= BN) return;

    float bb[32]; float nb = 0.f;
    const float4* F2 = (const float4*)(fea2 + (size_t)g * 32);
#pragma unroll
    for (int q = 0; q < 8; q++) {
        float4 w = F2[q];
        nb = fmaf(w.x,w.x, fmaf(w.y,w.y, fmaf(w.z,w.z, fmaf(w.w,w.w, nb))));
        float s = 2.f * LOG2E;
        bb[4*q] = s*w.x; bb[4*q+1] = s*w.y; bb[4*q+2] = s*w.z; bb[4*q+3] = s*w.w;
    }
    u32* Bf = (u32*)&g_Bf[(size_t)g * 64];
#pragma unroll
    for (int k = 0; k < 16; k++) {
        u16 h0 = f2bf(bb[2*k]),   l0 = f2bf(bb[2*k]   - bf2f(f2bf(bb[2*k])));
        u16 h1 = f2bf(bb[2*k+1]), l1 = f2bf(bb[2*k+1] - bf2f(f2bf(bb[2*k+1])));
        Bf[k]      = pk(h0, h1);
        Bf[16 + k] = pk(l0, l1);
    }
    g_cf[g] = -nb * LOG2E;

    float u0 = points[(size_t)g*3+0] * SIGMA_INV;
    float u1 = points[(size_t)g*3+1] * SIGMA_INV;
    float u2 = points[(size_t)g*3+2] * SIGMA_INV;
    float s = 2.f * LOG2E;
    g_vj[g] = make_float4(s*u0, s*u1, s*u2, -(u0*u0 + u1*u1 + u2*u2) * LOG2E);
}

// ---------- init ----------
__global__ void init_kernel(float* out, int B)
{
    if (threadIdx.x < B) out[threadIdx.x] = 0.f;
}

// ---------- main (rt=2, MT=128, dedup operands, 4 blocks/SM) ----------
__global__ __launch_bounds__(128, 4) void main_kernel(int N)
{
    __shared__ __align__(16) ull sBfU[128 * 16];
    __shared__ __align__(16) float4 sVj[128];
    __shared__ float sCf[128];

    const int tid = threadIdx.x;
    const int w = tid >> 5, l = tid & 31, g = l >> 2, t = l & 3;
    const int rowtile = blockIdx.x >> 4;
    const int chunk   = blockIdx.x & 15;
    const int rowbase = rowtile * MT;
    const int b  = rowbase / N;
    const int jc = N / JCH;                 // 256
    const int j0 = b * N + chunk * jc;
    const int ntiles = jc / NT;             // 2

    const u32* Af = (const u32*)g_Af;

    // A fragments: (ah,ks0)(ah,ks1)(al,ks0)(al,ks1) per rt
    u32 af[2][4][4];
    float cq[4];
    float4 u_h[4];
#pragma unroll
    for (int rt = 0; rt < 2; rt++) {
        int r0 = rowbase + 32 * w + 16 * rt + g;
#pragma unroll
        for (int q = 0; q < 4; q++) {
            int wbase = 8 * q + t;
            af[rt][q][0] = Af[(size_t)r0 * 32 + wbase];
            af[rt][q][1] = Af[(size_t)(r0 + 8) * 32 + wbase];
            af[rt][q][2] = Af[(size_t)r0 * 32 + wbase + 4];
            af[rt][q][3] = Af[(size_t)(r0 + 8) * 32 + wbase + 4];
        }
        cq[2*rt]     = g_rc[r0];
        cq[2*rt + 1] = g_rc[r0 + 8];
        u_h[2*rt]     = g_ui[r0];
        u_h[2*rt + 1] = g_ui[r0 + 8];
    }

    // hoisted shared-load offsets for B fragments (constant over ns, jt)
    const int rot = 4 * (g & 3);
    const int offH0 = (t + rot) & 15;
    const int offH1 = (4 + t + rot) & 15;
    const int offL0 = (8 + t + rot) & 15;
    const int offL1 = (12 + t + rot) & 15;

    ull Z[4] = {0,0,0,0}, S[4] = {0,0,0,0};
    float Aa[4] = {0.f, 0.f, 0.f, 0.f};

    for (int jt = 0; jt < ntiles; jt++) {
        __syncthreads();
        const int jrow = j0 + jt * NT;
        // stage feature B: thread = row; 8 uint4 -> 16 paired ulls, rotated
        {
            const uint4* src = (const uint4*)&g_Bf[(size_t)(jrow + tid) * 64];
            ull* dstrow = &sBfU[tid * 16];
            const int rot4 = 4 * (tid & 3);
#pragma unroll
            for (int u = 0; u < 4; u++) {
                uint4 lo = src[2 * u], hi = src[2 * u + 1];
                int base = (4 * u + rot4) & 15;
                *(uint4*)&dstrow[base]     = make_uint4(lo.x, hi.x, lo.y, hi.y);
                *(uint4*)&dstrow[base + 2] = make_uint4(lo.z, hi.z, lo.w, hi.w);
            }
            sVj[tid] = g_vj[jrow + tid];
            sCf[tid] = g_cf[jrow + tid];
        }
        __syncthreads();

#pragma unroll 2
        for (int ns = 0; ns < 16; ns++) {
            const int n = ns * 8 + g;
            const ull* rowF = &sBfU[n * 16];
            ull Fbh0 = rowF[offH0];
            ull Fbh1 = rowF[offH1];
            ull Fbl0 = rowF[offL0];
            ull Fbl1 = rowF[offL1];

            const int c0 = ns * 8 + 2 * t;
            float4 vA = sVj[c0];
            float4 vB = sVj[c0 + 1];
            float2 cf2 = *(const float2*)&sCf[c0];

            u32 bh0l, bh0h, bh1l, bh1h, bl0l, bl0h, bl1l, bl1h;
            unpack2u(Fbh0, bh0l, bh0h);
            unpack2u(Fbh1, bh1l, bh1h);
            unpack2u(Fbl0, bl0l, bl0h);
            unpack2u(Fbl1, bl1l, bl1h);

#pragma unroll
            for (int rt = 0; rt < 2; rt++) {
                const int h0 = 2 * rt, h1 = 2 * rt + 1;
                // chain A init = cq (row const), chain B init = cf (col const)
                float a0 = cq[h0], a1 = cq[h0], a2 = cq[h1], a3 = cq[h1];
                float b0 = cf2.x, b1 = cf2.y, b2 = cf2.x, b3 = cf2.y;
                mma16816(a0, a1, a2, a3, af[rt][0], bh0l, bh0h);   // ah0 * bh0
                mma16816(b0, b1, b2, b3, af[rt][1], bh1l, bh1h);   // ah1 * bh1
                mma16816(a0, a1, a2, a3, af[rt][2], bh0l, bh0h);   // al0 * bh0
                mma16816(b0, b1, b2, b3, af[rt][3], bh1l, bh1h);   // al1 * bh1
                mma16816(a0, a1, a2, a3, af[rt][0], bl0l, bl0h);   // ah0 * bl0
                mma16816(b0, b1, b2, b3, af[rt][1], bl1l, bl1h);   // ah1 * bl1

                {
                    float sq = a0 + b0;
                    float sp = fmaf(u_h[h0].x, vA.x, fmaf(u_h[h0].y, vA.y,
                               fmaf(u_h[h0].z, vA.z, u_h[h0].w + vA.w)));
                    float eq = ex2f(sq), ep = ex2f(sp);
                    ull e = pack2(eq, ep);
                    Z[h0] = f2add(Z[h0], e); S[h0] = f2fma(e, e, S[h0]);
                    Aa[h0] = fmaf(ep, eq, Aa[h0]);
                }
                {
                    float sq = a1 + b1;
                    float sp = fmaf(u_h[h0].x, vB.x, fmaf(u_h[h0].y, vB.y,
                               fmaf(u_h[h0].z, vB.z, u_h[h0].w + vB.w)));
                    float eq = ex2f(sq), ep = ex2f(sp);
                    ull e = pack2(eq, ep);
                    Z[h0] = f2add(Z[h0], e); S[h0] = f2fma(e, e, S[h0]);
                    Aa[h0] = fmaf(ep, eq, Aa[h0]);
                }
                {
                    float sq = a2 + b2;
                    float sp = fmaf(u_h[h1].x, vA.x, fmaf(u_h[h1].y, vA.y,
                               fmaf(u_h[h1].z, vA.z, u_h[h1].w + vA.w)));
                    float eq = ex2f(sq), ep = ex2f(sp);
                    ull e = pack2(eq, ep);
                    Z[h1] = f2add(Z[h1], e); S[h1] = f2fma(e, e, S[h1]);
                    Aa[h1] = fmaf(ep, eq, Aa[h1]);
                }
                {
                    float sq = a3 + b3;
                    float sp = fmaf(u_h[h1].x, vB.x, fmaf(u_h[h1].y, vB.y,
                               fmaf(u_h[h1].z, vB.z, u_h[h1].w + vB.w)));
                    float eq = ex2f(sq), ep = ex2f(sp);
                    ull e = pack2(eq, ep);
                    Z[h1] = f2add(Z[h1], e); S[h1] = f2fma(e, e, S[h1]);
                    Aa[h1] = fmaf(ep, eq, Aa[h1]);
                }
            }
        }
    }

    // quad-reduce over t, write partials
#pragma unroll
    for (int h = 0; h < 4; h++) {
        float Zq, Zp, C, Bb;
        unpack2(Z[h], Zq, Zp);
        unpack2(S[h], C, Bb);
        float A_ = Aa[h];
#pragma unroll
        for (int m = 1; m <= 2; m <<= 1) {
            Zq += __shfl_xor_sync(0xffffffffu, Zq, m);
            Zp += __shfl_xor_sync(0xffffffffu, Zp, m);
            C  += __shfl_xor_sync(0xffffffffu, C,  m);
            Bb += __shfl_xor_sync(0xffffffffu, Bb, m);
            A_ += __shfl_xor_sync(0xffffffffu, A_, m);
        }
        if (t == 0) {
            int row = rowbase + 32 * w + 16 * (h >> 1) + 8 * (h & 1) + g;
            size_t p = ((size_t)row * JCH + chunk) * 2;
            g_part[p + 0] = make_float4(Zq, A_, C, Zp);
            g_part[p + 1] = make_float4(Bb, 0.f, 0.f, 0.f);
        }
    }
}

// ---------- reduce: 4 threads per row, 16 chunks ----------
__global__ __launch_bounds__(128) void reduce_kernel(
    const float* __restrict__ weights,
    float* __restrict__ out, int N)
{
    __shared__ float sred[4];
    const int tid = threadIdx.x;
    const int r = blockIdx.x * 32 + (tid >> 2);
    const int t = tid & 3;
    const int b = (blockIdx.x * 32) / N;

    const float4* base = &g_part[(size_t)r * JCH * 2];
    float Zq = 0.f, A = 0.f, C = 0.f, Zp = 0.f, Bb = 0.f;
#pragma unroll
    for (int kk = 0; kk < 4; kk++) {
        int k = t + 4 * kk;
        float4 p0 = base[2 * k + 0];
        float4 p1 = base[2 * k + 1];
        Zq += p0.x; A += p0.y; C += p0.z; Zp += p0.w; Bb += p1.x;
    }
#pragma unroll
    for (int m = 1; m <= 2; m <<= 1) {
        Zq += __shfl_xor_sync(0xffffffffu, Zq, m);
        Zp += __shfl_xor_sync(0xffffffffu, Zp, m);
        C  += __shfl_xor_sync(0xffffffffu, C,  m);
        Bb += __shfl_xor_sync(0xffffffffu, Bb, m);
        A  += __shfl_xor_sync(0xffffffffu, A,  m);
    }
    float v = 0.f;
    if (t == 0) {
        float izp = 1.f / Zp, izq = 1.f / Zq;
        float loss = Bb * izp * izp - 2.f * A * izp * izq + C * izq * izq;
        v = weights[r] * loss;
    }
#pragma unroll
    for (int off = 16; off > 0; off >>= 1)
        v += __shfl_down_sync(0xffffffffu, v, off);
    if ((tid & 31) == 0) sred[tid >> 5] = v;
    __syncthreads();
    if (tid == 0) {
        atomicAdd(&out[b], sred[0] + sred[1] + sred[2] + sred[3]);
    }
}

extern "C" void kernel_launch(void* const* d_in, const int* in_sizes, int n_in,
                              void* d_out, int out_size)
{
    const float* points  = (const float*)d_in[0];  // [B,N,3]
    const float* fea1    = (const float*)d_in[1];  // [B,N,32]
    const float* fea2    = (const float*)d_in[2];  // [B,N,32]
    const float* weights = (const float*)d_in[3];  // [B,N]

    int BN = in_sizes[3];
    int B  = out_size;
    int N  = BN / B;

    // main is absolute launch index 3 (the profiled slot).
    prep_A<<<(BN + 127) / 128, 128>>>(points, fea1, BN);
    prep_B<<<(BN + 127) / 128, 128>>>(points, fea2, BN);
    init_kernel<<<1, 32>>>((float*)d_out, B);

    int rowtiles = BN / MT;                       // 64
    main_kernel<<<rowtiles * JCH, 128>>>(N);      // 1024 blocks

    reduce_kernel<<<BN / 32, 128>>>(weights, (float*)d_out, N);
}